// round 1
// baseline (speedup 1.0000x reference)
#include <cuda_runtime.h>
#include <math.h>

#define SS 2048
#define DD 2048
#define HH 16
#define EE 128
#define NQKV (3*EE)        // 384
#define NTOT (HH*NQKV)     // 6144

// Scratch for projected Q/K/V: layout qkv[s][h*384 + j], j: 0..127 Q, 128..255 K, 256..383 V
__device__ float g_qkv[(size_t)SS * NTOT];

// ---------------------------------------------------------------------------
// Kernel 1: QKV projection as a single GEMM  C[S, 6144] = X[S, 2048] @ W
// W logical element (d, n) with n = h*384 + j lives at W[h*D*384 + d*384 + j].
// Each 128-wide N tile lies entirely within one head (384 = 3*128).
// ---------------------------------------------------------------------------
#define GBM 128
#define GBN 128
#define GBK 16

__global__ __launch_bounds__(256) void qkv_gemm_kernel(
    const float* __restrict__ X, const float* __restrict__ W) {
  __shared__ float As[GBM][GBK + 1];   // [m][k]
  __shared__ float Bs[GBK][GBN + 4];   // [k][n], pad 4 keeps 16B alignment

  const int tid = threadIdx.x;
  const int m0 = blockIdx.y * GBM;
  const int n0 = blockIdx.x * GBN;
  const int ty = tid >> 4;             // 0..15
  const int tx = tid & 15;             // 0..15

  const int h  = n0 / NQKV;
  const int j0 = n0 % NQKV;
  const float* Wh = W + (size_t)h * DD * NQKV + j0;

  float acc[8][8];
  #pragma unroll
  for (int i = 0; i < 8; i++)
    #pragma unroll
    for (int j = 0; j < 8; j++) acc[i][j] = 0.f;

  for (int k0 = 0; k0 < DD; k0 += GBK) {
    // Load A tile 128x16 (coalesced over k within rows of X)
    #pragma unroll
    for (int i = 0; i < 8; i++) {
      int idx = tid + i * 256;         // 0..2047
      int kk = idx & 15, m = idx >> 4;
      As[m][kk] = X[(size_t)(m0 + m) * DD + k0 + kk];
    }
    // Load B tile 16x128 (coalesced over n)
    #pragma unroll
    for (int i = 0; i < 8; i++) {
      int idx = tid + i * 256;         // 0..2047
      int n = idx & 127, kk = idx >> 7;
      Bs[kk][n] = Wh[(size_t)(k0 + kk) * NQKV + n];
    }
    __syncthreads();

    #pragma unroll
    for (int kk = 0; kk < GBK; kk++) {
      float a[8], b[8];
      #pragma unroll
      for (int i = 0; i < 8; i++) a[i] = As[ty * 8 + i][kk];
      float4 b0 = *(const float4*)&Bs[kk][tx * 8];
      float4 b1 = *(const float4*)&Bs[kk][tx * 8 + 4];
      b[0] = b0.x; b[1] = b0.y; b[2] = b0.z; b[3] = b0.w;
      b[4] = b1.x; b[5] = b1.y; b[6] = b1.z; b[7] = b1.w;
      #pragma unroll
      for (int i = 0; i < 8; i++)
        #pragma unroll
        for (int j = 0; j < 8; j++)
          acc[i][j] = fmaf(a[i], b[j], acc[i][j]);
    }
    __syncthreads();
  }

  #pragma unroll
  for (int i = 0; i < 8; i++) {
    float* crow = &g_qkv[(size_t)(m0 + ty * 8 + i) * NTOT + n0 + tx * 8];
    #pragma unroll
    for (int j = 0; j < 8; j++) crow[j] = acc[i][j];
  }
}

// ---------------------------------------------------------------------------
// Kernel 2: flash attention per head. BQ=64 query rows per block, stream K/V
// in BKV=64 tiles with online softmax. 256 threads.
// ---------------------------------------------------------------------------
#define BQ  64
#define BKV 64

#define QS_STRIDE 129
#define KS_STRIDE 129
#define SS_STRIDE 65

// dynamic smem layout (floats)
#define OFF_Q   0
#define OFF_K   (OFF_Q + BQ * QS_STRIDE)
#define OFF_V   (OFF_K + BKV * KS_STRIDE)
#define OFF_S   (OFF_V + BKV * EE)
#define OFF_M   (OFF_S + BQ * SS_STRIDE)
#define OFF_L   (OFF_M + BQ)
#define OFF_A   (OFF_L + BQ)
#define SMEM_FLOATS (OFF_A + BQ)
#define SMEM_BYTES  (SMEM_FLOATS * 4)

__global__ __launch_bounds__(256) void attn_kernel(float* __restrict__ out) {
  extern __shared__ float sm[];
  float* Qs  = sm + OFF_Q;   // [64][129]
  float* Ks  = sm + OFF_K;   // [64][129]
  float* Vs  = sm + OFF_V;   // [64][128]
  float* Sm  = sm + OFF_S;   // [64][65] scores / probs
  float* m_s = sm + OFF_M;
  float* l_s = sm + OFF_L;
  float* a_s = sm + OFF_A;

  const int tid = threadIdx.x;
  const int h   = blockIdx.y;
  const int q0  = blockIdx.x * BQ;
  const float scale = 0.08838834764831845f;  // 1/sqrt(128)

  // Load Q tile (pre-scaled)
  #pragma unroll
  for (int i = 0; i < 32; i++) {
    int idx = tid + i * 256;               // 0..8191
    int d = idx & 127, r = idx >> 7;
    Qs[r * QS_STRIDE + d] =
        g_qkv[(size_t)(q0 + r) * NTOT + h * NQKV + d] * scale;
  }
  if (tid < BQ) { m_s[tid] = -INFINITY; l_s[tid] = 0.f; }

  // PV / output mapping: 8 rows x 4 cols per thread
  const int r0 = (tid >> 5) * 8;           // row base
  const int c0 = (tid & 31) * 4;           // col base
  float o[8][4];
  #pragma unroll
  for (int i = 0; i < 8; i++)
    #pragma unroll
    for (int j = 0; j < 4; j++) o[i][j] = 0.f;

  // score-phase mapping: 4x4 micro-tile on a 16x16 thread grid
  const int sqr = (tid >> 4) * 4;
  const int skc = (tid & 15) * 4;

  for (int t0 = 0; t0 < SS; t0 += BKV) {
    __syncthreads();  // previous tile's consumers done before overwrite

    // Load K and V tiles (coalesced over d)
    #pragma unroll
    for (int i = 0; i < 32; i++) {
      int idx = tid + i * 256;
      int d = idx & 127, r = idx >> 7;
      const float* base = &g_qkv[(size_t)(t0 + r) * NTOT + h * NQKV];
      Ks[r * KS_STRIDE + d] = base[EE + d];
      Vs[r * EE + d]        = base[2 * EE + d];
    }
    __syncthreads();

    // Scores: S[sqr..+3][skc..+3] = Q . K^T
    float sacc[4][4];
    #pragma unroll
    for (int i = 0; i < 4; i++)
      #pragma unroll
      for (int j = 0; j < 4; j++) sacc[i][j] = 0.f;

    #pragma unroll 8
    for (int d = 0; d < EE; d++) {
      float a[4], b[4];
      #pragma unroll
      for (int i = 0; i < 4; i++) a[i] = Qs[(sqr + i) * QS_STRIDE + d];
      #pragma unroll
      for (int j = 0; j < 4; j++) b[j] = Ks[(skc + j) * KS_STRIDE + d];
      #pragma unroll
      for (int i = 0; i < 4; i++)
        #pragma unroll
        for (int j = 0; j < 4; j++)
          sacc[i][j] = fmaf(a[i], b[j], sacc[i][j]);
    }
    #pragma unroll
    for (int i = 0; i < 4; i++)
      #pragma unroll
      for (int j = 0; j < 4; j++)
        Sm[(sqr + i) * SS_STRIDE + skc + j] = sacc[i][j];
    __syncthreads();

    // Online softmax update, one thread per row
    if (tid < BQ) {
      float mold = m_s[tid];
      float mx = mold;
      float* srow = &Sm[tid * SS_STRIDE];
      #pragma unroll 8
      for (int k = 0; k < BKV; k++) mx = fmaxf(mx, srow[k]);
      float al = __expf(mold - mx);       // 0 on first tile (mold = -inf)
      float sum = 0.f;
      #pragma unroll 8
      for (int k = 0; k < BKV; k++) {
        float p = __expf(srow[k] - mx);
        srow[k] = p;
        sum += p;
      }
      l_s[tid] = l_s[tid] * al + sum;
      m_s[tid] = mx;
      a_s[tid] = al;
    }
    __syncthreads();

    // Rescale accumulators and add P @ V
    float al[8];
    #pragma unroll
    for (int i = 0; i < 8; i++) al[i] = a_s[r0 + i];
    #pragma unroll
    for (int i = 0; i < 8; i++)
      #pragma unroll
      for (int j = 0; j < 4; j++) o[i][j] *= al[i];

    #pragma unroll 4
    for (int k = 0; k < BKV; k++) {
      float4 v = *(const float4*)&Vs[k * EE + c0];
      #pragma unroll
      for (int i = 0; i < 8; i++) {
        float p = Sm[(r0 + i) * SS_STRIDE + k];
        o[i][0] = fmaf(p, v.x, o[i][0]);
        o[i][1] = fmaf(p, v.y, o[i][1]);
        o[i][2] = fmaf(p, v.z, o[i][2]);
        o[i][3] = fmaf(p, v.w, o[i][3]);
      }
    }
  }

  // Final normalize and write out[s][h*128 + e]
  #pragma unroll
  for (int i = 0; i < 8; i++) {
    float inv = 1.f / l_s[r0 + i];
    float* op = &out[(size_t)(q0 + r0 + i) * (HH * EE) + h * EE + c0];
    #pragma unroll
    for (int j = 0; j < 4; j++) op[j] = o[i][j] * inv;
  }
}

// ---------------------------------------------------------------------------
extern "C" void kernel_launch(void* const* d_in, const int* in_sizes, int n_in,
                              void* d_out, int out_size) {
  const float* x = (const float*)d_in[0];     // [2048, 2048]
  const float* w = (const float*)d_in[1];     // [16, 2048, 384]
  float* out = (float*)d_out;                 // [2048, 2048]

  (void)in_sizes; (void)n_in; (void)out_size;

  cudaFuncSetAttribute(attn_kernel,
                       cudaFuncAttributeMaxDynamicSharedMemorySize, SMEM_BYTES);

  dim3 ggrid(NTOT / GBN, SS / GBM);           // (48, 16)
  qkv_gemm_kernel<<<ggrid, 256>>>(x, w);

  dim3 agrid(SS / BQ, HH);                    // (32, 16)
  attn_kernel<<<agrid, 256, SMEM_BYTES>>>(out);
}

// round 3
// speedup vs baseline: 1.5019x; 1.5019x over previous
#include <cuda_runtime.h>
#include <cuda_bf16.h>
#include <math.h>
#include <stdint.h>

#define SS 2048
#define DD 2048
#define HH 16
#define EE 128
#define NQKV (3*EE)        // 384
#define NTOT (HH*NQKV)     // 6144

// ---------------------------------------------------------------------------
// Device scratch (static — no runtime allocation allowed)
// ---------------------------------------------------------------------------
__device__ float g_qkv[(size_t)SS * NTOT];                       // 50 MB
__device__ __nv_bfloat16 g_xhi[(size_t)SS * DD];                 // 8 MB
__device__ __nv_bfloat16 g_xlo[(size_t)SS * DD];                 // 8 MB
__device__ __nv_bfloat16 g_wthi[(size_t)NTOT * DD];              // 25 MB
__device__ __nv_bfloat16 g_wtlo[(size_t)NTOT * DD];              // 25 MB

// ---------------------------------------------------------------------------
// PTX helpers (base-target-safe: mma.sync / ldmatrix / cp.async)
// ---------------------------------------------------------------------------
__device__ __forceinline__ uint32_t smem_u32(const void* p) {
  uint32_t a;
  asm("{ .reg .u64 t; cvta.to.shared.u64 t, %1; cvt.u32.u64 %0, t; }"
      : "=r"(a) : "l"(p));
  return a;
}

#define LDSM_X4(r, a)                                                        \
  asm volatile("ldmatrix.sync.aligned.m8n8.x4.shared.b16 {%0,%1,%2,%3}, [%4];" \
               : "=r"((r)[0]), "=r"((r)[1]), "=r"((r)[2]), "=r"((r)[3])      \
               : "r"(a))

__device__ __forceinline__ void mma16816(float* c, const uint32_t* a,
                                         const uint32_t* b) {
  asm volatile(
      "mma.sync.aligned.m16n8k16.row.col.f32.bf16.bf16.f32 "
      "{%0,%1,%2,%3}, {%4,%5,%6,%7}, {%8,%9}, {%0,%1,%2,%3};"
      : "+f"(c[0]), "+f"(c[1]), "+f"(c[2]), "+f"(c[3])
      : "r"(a[0]), "r"(a[1]), "r"(a[2]), "r"(a[3]), "r"(b[0]), "r"(b[1]));
}

#define CP16(sm, gp)                                                   \
  asm volatile("cp.async.cg.shared.global [%0], [%1], 16;" ::          \
               "r"(sm), "l"(gp))
#define CP_COMMIT() asm volatile("cp.async.commit_group;" ::: "memory")
#define CP_WAIT(n)  asm volatile("cp.async.wait_group %0;" :: "n"(n) : "memory")

// ---------------------------------------------------------------------------
// Prep kernel 1: X fp32 -> (hi, lo) bf16 pair
// ---------------------------------------------------------------------------
__global__ __launch_bounds__(256) void convx_kernel(const float* __restrict__ X) {
  size_t i = (size_t)blockIdx.x * blockDim.x + threadIdx.x;
  float4 v = ((const float4*)X)[i];
  __nv_bfloat16 h0 = __float2bfloat16(v.x), h1 = __float2bfloat16(v.y);
  __nv_bfloat16 h2 = __float2bfloat16(v.z), h3 = __float2bfloat16(v.w);
  __nv_bfloat162* hip = (__nv_bfloat162*)g_xhi;
  __nv_bfloat162* lop = (__nv_bfloat162*)g_xlo;
  hip[2*i]   = __nv_bfloat162(h0, h1);
  hip[2*i+1] = __nv_bfloat162(h2, h3);
  lop[2*i]   = __nv_bfloat162(__float2bfloat16(v.x - __bfloat162float(h0)),
                              __float2bfloat16(v.y - __bfloat162float(h1)));
  lop[2*i+1] = __nv_bfloat162(__float2bfloat16(v.z - __bfloat162float(h2)),
                              __float2bfloat16(v.w - __bfloat162float(h3)));
}

// ---------------------------------------------------------------------------
// Prep kernel 2: W[h][d][j] -> Wt[n=h*384+j][d] as (hi, lo) bf16
// ---------------------------------------------------------------------------
__global__ __launch_bounds__(256) void convw_kernel(const float* __restrict__ W) {
  __shared__ float t[32][33];
  int h = blockIdx.z;
  int j0 = blockIdx.x * 32, d0 = blockIdx.y * 32;
  int tx = threadIdx.x & 31, ty = threadIdx.x >> 5;      // ty: 0..7
  const float* Wh = W + (size_t)h * DD * NQKV;
  #pragma unroll
  for (int i = 0; i < 4; i++) {
    int d = d0 + ty + i * 8;
    t[ty + i * 8][tx] = Wh[(size_t)d * NQKV + j0 + tx];
  }
  __syncthreads();
  #pragma unroll
  for (int i = 0; i < 4; i++) {
    int j = j0 + ty + i * 8;
    float v = t[tx][ty + i * 8];                          // = W[h][d0+tx][j]
    size_t o = (size_t)(h * NQKV + j) * DD + d0 + tx;
    __nv_bfloat16 hi = __float2bfloat16(v);
    g_wthi[o] = hi;
    g_wtlo[o] = __float2bfloat16(v - __bfloat162float(hi));
  }
}

// ---------------------------------------------------------------------------
// QKV GEMM via mma.sync (bf16x3 split precision).
// C[2048, 6144] = X @ Wt^T. Block 128x128, BK=32, 8 warps (2m x 4n),
// warp tile 64x32, cp.async double buffer.
// ---------------------------------------------------------------------------
#define BM 128
#define BN 128
#define BK 32
#define NSTAGE_K (DD / BK)        // 64 k-iterations

#define ROWB 80                   // smem bytes per 32-elem bf16 row (16B pad)
#define TILEB (128 * ROWB)        // 10240 per (hi|lo)(A|B) tile
#define STAGEB (4 * TILEB)        // 40960
#define GEMM_SMEM (2 * STAGEB)    // 81920

__global__ __launch_bounds__(256, 1) void qkv_mma_kernel() {
  extern __shared__ char smem[];
  const uint32_t sb = smem_u32(smem);
  const int tid = threadIdx.x;
  const int lane = tid & 31;
  const int wid = tid >> 5;
  const int warp_m = wid >> 2;           // 0..1
  const int warp_n = wid & 3;            // 0..3
  const int m0 = blockIdx.y * BM;
  const int n0 = blockIdx.x * BN;

  float acc[4][4][4];
  #pragma unroll
  for (int i = 0; i < 4; i++)
    #pragma unroll
    for (int j = 0; j < 4; j++)
      #pragma unroll
      for (int q = 0; q < 4; q++) acc[i][j][q] = 0.f;

  // per-thread load mapping: 2 chunks per tile per stage
  const int ld_r0 = (tid * 2) >> 2;          // row of chunk pair? (see below)
  // chunk idx = tid + i*256, i=0..1; r = idx>>2 (0..127), cc = idx&3

  // ldmatrix base addresses (per stage added later)
  // A: lane -> row (l&15), col-half (l>>4)
  const uint32_t a_lrow = (uint32_t)(lane & 15);
  const uint32_t a_lcol = (uint32_t)((lane >> 4) * 16);
  // B: lanes 0-7: n+ (l&7) klo | 8-15: same rows khi | 16-23: n+8+(l&7) klo | 24-31: khi
  const uint32_t b_lrow = (uint32_t)((lane & 7) + ((lane >> 4) << 3));
  const uint32_t b_lcol = (uint32_t)(((lane >> 3) & 1) * 16);

  // --------- stage loader ---------
  auto load_stage = [&](int buf, int c) {
    const int k0 = c * BK;
    const uint32_t sbase = sb + buf * STAGEB;
    #pragma unroll
    for (int i = 0; i < 2; i++) {
      int idx = tid + i * 256;             // 0..511
      int r = idx >> 2, cc = idx & 3;
      uint32_t so = sbase + (uint32_t)(r * ROWB + cc * 16);
      size_t goA = (size_t)(m0 + r) * DD + k0 + cc * 8;
      size_t goB = (size_t)(n0 + r) * DD + k0 + cc * 8;
      CP16(so,              g_xhi  + goA);
      CP16(so + TILEB,      g_xlo  + goA);
      CP16(so + 2 * TILEB,  g_wthi + goB);
      CP16(so + 3 * TILEB,  g_wtlo + goB);
    }
  };

  load_stage(0, 0);
  CP_COMMIT();

  for (int c = 0; c < NSTAGE_K; c++) {
    if (c + 1 < NSTAGE_K) {
      load_stage((c + 1) & 1, c + 1);
      CP_COMMIT();
      CP_WAIT(1);
    } else {
      CP_WAIT(0);
    }
    __syncthreads();

    const uint32_t sbase = sb + (c & 1) * STAGEB;
    const uint32_t sAh = sbase;
    const uint32_t sAl = sbase + TILEB;
    const uint32_t sBh = sbase + 2 * TILEB;
    const uint32_t sBl = sbase + 3 * TILEB;

    #pragma unroll
    for (int ks = 0; ks < 2; ks++) {
      const uint32_t kb = (uint32_t)(ks * 32);   // 16 bf16 = 32 bytes

      uint32_t ah[4][4], al[4][4];
      #pragma unroll
      for (int mt = 0; mt < 4; mt++) {
        uint32_t row0 = (uint32_t)(warp_m * 64 + mt * 16);
        uint32_t off = (row0 + a_lrow) * ROWB + kb + a_lcol;
        LDSM_X4(ah[mt], sAh + off);
        LDSM_X4(al[mt], sAl + off);
      }
      uint32_t bh[4][2], bl[4][2];
      #pragma unroll
      for (int np = 0; np < 2; np++) {
        uint32_t nrow0 = (uint32_t)(warp_n * 32 + np * 16);
        uint32_t off = (nrow0 + b_lrow) * ROWB + kb + b_lcol;
        uint32_t q[4];
        LDSM_X4(q, sBh + off);
        bh[2*np][0] = q[0]; bh[2*np][1] = q[1];
        bh[2*np+1][0] = q[2]; bh[2*np+1][1] = q[3];
        LDSM_X4(q, sBl + off);
        bl[2*np][0] = q[0]; bl[2*np][1] = q[1];
        bl[2*np+1][0] = q[2]; bl[2*np+1][1] = q[3];
      }
      #pragma unroll
      for (int mt = 0; mt < 4; mt++) {
        #pragma unroll
        for (int nt = 0; nt < 4; nt++) {
          mma16816(acc[mt][nt], ah[mt], bh[nt]);
          mma16816(acc[mt][nt], ah[mt], bl[nt]);
          mma16816(acc[mt][nt], al[mt], bh[nt]);
        }
      }
    }
    __syncthreads();
  }

  // Epilogue: fragment -> g_qkv (fp32)
  const int g = lane >> 2, tig = lane & 3;
  #pragma unroll
  for (int mt = 0; mt < 4; mt++) {
    int row = m0 + warp_m * 64 + mt * 16 + g;
    #pragma unroll
    for (int nt = 0; nt < 4; nt++) {
      int col = n0 + warp_n * 32 + nt * 8 + tig * 2;
      *(float2*)&g_qkv[(size_t)row * NTOT + col] =
          make_float2(acc[mt][nt][0], acc[mt][nt][1]);
      *(float2*)&g_qkv[(size_t)(row + 8) * NTOT + col] =
          make_float2(acc[mt][nt][2], acc[mt][nt][3]);
    }
  }
}

// ---------------------------------------------------------------------------
// Flash attention per head (unchanged from passing R1 version).
// ---------------------------------------------------------------------------
#define BQ  64
#define BKV 64

#define QS_STRIDE 129
#define KS_STRIDE 129
#define SS_STRIDE 65

#define OFF_Q   0
#define OFF_K   (OFF_Q + BQ * QS_STRIDE)
#define OFF_V   (OFF_K + BKV * KS_STRIDE)
#define OFF_S   (OFF_V + BKV * EE)
#define OFF_M   (OFF_S + BQ * SS_STRIDE)
#define OFF_L   (OFF_M + BQ)
#define OFF_A   (OFF_L + BQ)
#define SMEM_FLOATS (OFF_A + BQ)
#define SMEM_BYTES  (SMEM_FLOATS * 4)

__global__ __launch_bounds__(256) void attn_kernel(float* __restrict__ out) {
  extern __shared__ float sm[];
  float* Qs  = sm + OFF_Q;
  float* Ks  = sm + OFF_K;
  float* Vs  = sm + OFF_V;
  float* Sm  = sm + OFF_S;
  float* m_s = sm + OFF_M;
  float* l_s = sm + OFF_L;
  float* a_s = sm + OFF_A;

  const int tid = threadIdx.x;
  const int h   = blockIdx.y;
  const int q0  = blockIdx.x * BQ;
  const float scale = 0.08838834764831845f;

  #pragma unroll
  for (int i = 0; i < 32; i++) {
    int idx = tid + i * 256;
    int d = idx & 127, r = idx >> 7;
    Qs[r * QS_STRIDE + d] =
        g_qkv[(size_t)(q0 + r) * NTOT + h * NQKV + d] * scale;
  }
  if (tid < BQ) { m_s[tid] = -INFINITY; l_s[tid] = 0.f; }

  const int r0 = (tid >> 5) * 8;
  const int c0 = (tid & 31) * 4;
  float o[8][4];
  #pragma unroll
  for (int i = 0; i < 8; i++)
    #pragma unroll
    for (int j = 0; j < 4; j++) o[i][j] = 0.f;

  const int sqr = (tid >> 4) * 4;
  const int skc = (tid & 15) * 4;

  for (int t0 = 0; t0 < SS; t0 += BKV) {
    __syncthreads();

    #pragma unroll
    for (int i = 0; i < 32; i++) {
      int idx = tid + i * 256;
      int d = idx & 127, r = idx >> 7;
      const float* base = &g_qkv[(size_t)(t0 + r) * NTOT + h * NQKV];
      Ks[r * KS_STRIDE + d] = base[EE + d];
      Vs[r * EE + d]        = base[2 * EE + d];
    }
    __syncthreads();

    float sacc[4][4];
    #pragma unroll
    for (int i = 0; i < 4; i++)
      #pragma unroll
      for (int j = 0; j < 4; j++) sacc[i][j] = 0.f;

    #pragma unroll 8
    for (int d = 0; d < EE; d++) {
      float a[4], b[4];
      #pragma unroll
      for (int i = 0; i < 4; i++) a[i] = Qs[(sqr + i) * QS_STRIDE + d];
      #pragma unroll
      for (int j = 0; j < 4; j++) b[j] = Ks[(skc + j) * KS_STRIDE + d];
      #pragma unroll
      for (int i = 0; i < 4; i++)
        #pragma unroll
        for (int j = 0; j < 4; j++)
          sacc[i][j] = fmaf(a[i], b[j], sacc[i][j]);
    }
    #pragma unroll
    for (int i = 0; i < 4; i++)
      #pragma unroll
      for (int j = 0; j < 4; j++)
        Sm[(sqr + i) * SS_STRIDE + skc + j] = sacc[i][j];
    __syncthreads();

    if (tid < BQ) {
      float mold = m_s[tid];
      float mx = mold;
      float* srow = &Sm[tid * SS_STRIDE];
      #pragma unroll 8
      for (int k = 0; k < BKV; k++) mx = fmaxf(mx, srow[k]);
      float al = __expf(mold - mx);
      float sum = 0.f;
      #pragma unroll 8
      for (int k = 0; k < BKV; k++) {
        float p = __expf(srow[k] - mx);
        srow[k] = p;
        sum += p;
      }
      l_s[tid] = l_s[tid] * al + sum;
      m_s[tid] = mx;
      a_s[tid] = al;
    }
    __syncthreads();

    float al[8];
    #pragma unroll
    for (int i = 0; i < 8; i++) al[i] = a_s[r0 + i];
    #pragma unroll
    for (int i = 0; i < 8; i++)
      #pragma unroll
      for (int j = 0; j < 4; j++) o[i][j] *= al[i];

    #pragma unroll 4
    for (int k = 0; k < BKV; k++) {
      float4 v = *(const float4*)&Vs[k * EE + c0];
      #pragma unroll
      for (int i = 0; i < 8; i++) {
        float p = Sm[(r0 + i) * SS_STRIDE + k];
        o[i][0] = fmaf(p, v.x, o[i][0]);
        o[i][1] = fmaf(p, v.y, o[i][1]);
        o[i][2] = fmaf(p, v.z, o[i][2]);
        o[i][3] = fmaf(p, v.w, o[i][3]);
      }
    }
  }

  #pragma unroll
  for (int i = 0; i < 8; i++) {
    float inv = 1.f / l_s[r0 + i];
    float* op = &out[(size_t)(q0 + r0 + i) * (HH * EE) + h * EE + c0];
    #pragma unroll
    for (int j = 0; j < 4; j++) op[j] = o[i][j] * inv;
  }
}

// ---------------------------------------------------------------------------
extern "C" void kernel_launch(void* const* d_in, const int* in_sizes, int n_in,
                              void* d_out, int out_size) {
  const float* x = (const float*)d_in[0];     // [2048, 2048]
  const float* w = (const float*)d_in[1];     // [16, 2048, 384]
  float* out = (float*)d_out;                 // [2048, 2048]
  (void)in_sizes; (void)n_in; (void)out_size;

  cudaFuncSetAttribute(qkv_mma_kernel,
                       cudaFuncAttributeMaxDynamicSharedMemorySize, GEMM_SMEM);
  cudaFuncSetAttribute(attn_kernel,
                       cudaFuncAttributeMaxDynamicSharedMemorySize, SMEM_BYTES);

  convx_kernel<<<(SS * DD / 4) / 256, 256>>>(x);
  convw_kernel<<<dim3(NQKV / 32, DD / 32, HH), 256>>>(w);

  qkv_mma_kernel<<<dim3(NTOT / BN, SS / BM), 256, GEMM_SMEM>>>();

  attn_kernel<<<dim3(SS / BQ, HH), 256, SMEM_BYTES>>>(out);
}

// round 4
// speedup vs baseline: 3.2904x; 2.1909x over previous
#include <cuda_runtime.h>
#include <cuda_bf16.h>
#include <math.h>
#include <stdint.h>

#define SS 2048
#define DD 2048
#define HH 16
#define EE 128
#define NQKV (3*EE)        // 384
#define NTOT (HH*NQKV)     // 6144
#define SCALE 0.08838834764831845f

// ---------------------------------------------------------------------------
// Device scratch (static — no runtime allocation allowed)
// ---------------------------------------------------------------------------
__device__ __nv_bfloat16 g_xhi[(size_t)SS * DD];
__device__ __nv_bfloat16 g_xlo[(size_t)SS * DD];
__device__ __nv_bfloat16 g_wthi[(size_t)NTOT * DD];
__device__ __nv_bfloat16 g_wtlo[(size_t)NTOT * DD];
// Projected Q/K/V, split bf16, layout [h][s][e]  (Q pre-scaled by 1/sqrt(E))
__device__ __nv_bfloat16 g_qhi[(size_t)HH * SS * EE];
__device__ __nv_bfloat16 g_qlo[(size_t)HH * SS * EE];
__device__ __nv_bfloat16 g_khi[(size_t)HH * SS * EE];
__device__ __nv_bfloat16 g_klo[(size_t)HH * SS * EE];
__device__ __nv_bfloat16 g_vhi[(size_t)HH * SS * EE];
__device__ __nv_bfloat16 g_vlo[(size_t)HH * SS * EE];

// ---------------------------------------------------------------------------
// PTX helpers (base-target-safe)
// ---------------------------------------------------------------------------
__device__ __forceinline__ uint32_t smem_u32(const void* p) {
  uint32_t a;
  asm("{ .reg .u64 t; cvta.to.shared.u64 t, %1; cvt.u32.u64 %0, t; }"
      : "=r"(a) : "l"(p));
  return a;
}

#define LDSM_X4(r, a)                                                        \
  asm volatile("ldmatrix.sync.aligned.m8n8.x4.shared.b16 {%0,%1,%2,%3}, [%4];" \
               : "=r"((r)[0]), "=r"((r)[1]), "=r"((r)[2]), "=r"((r)[3])      \
               : "r"(a))

#define LDSM_X4_T(r, a)                                                      \
  asm volatile("ldmatrix.sync.aligned.m8n8.x4.trans.shared.b16 {%0,%1,%2,%3}, [%4];" \
               : "=r"((r)[0]), "=r"((r)[1]), "=r"((r)[2]), "=r"((r)[3])      \
               : "r"(a))

__device__ __forceinline__ void mma16816(float* c, const uint32_t* a,
                                         const uint32_t* b) {
  asm volatile(
      "mma.sync.aligned.m16n8k16.row.col.f32.bf16.bf16.f32 "
      "{%0,%1,%2,%3}, {%4,%5,%6,%7}, {%8,%9}, {%0,%1,%2,%3};"
      : "+f"(c[0]), "+f"(c[1]), "+f"(c[2]), "+f"(c[3])
      : "r"(a[0]), "r"(a[1]), "r"(a[2]), "r"(a[3]), "r"(b[0]), "r"(b[1]));
}

#define CP16(sm, gp)                                                   \
  asm volatile("cp.async.cg.shared.global [%0], [%1], 16;" ::          \
               "r"(sm), "l"(gp))
#define CP_COMMIT() asm volatile("cp.async.commit_group;" ::: "memory")
#define CP_WAIT(n)  asm volatile("cp.async.wait_group %0;" :: "n"(n) : "memory")

// split a float into bf16 hi + bf16 lo (residual)
__device__ __forceinline__ void splitf(float v, float& hf, float& lf) {
  __nv_bfloat16 h = __float2bfloat16(v);
  hf = __bfloat162float(h);
  lf = v - hf;
}
__device__ __forceinline__ uint32_t pack2(float a, float b) {
  __nv_bfloat162 t = __floats2bfloat162_rn(a, b);   // a -> low half
  return *(uint32_t*)&t;
}

// ---------------------------------------------------------------------------
// Prep kernel 1: X fp32 -> (hi, lo) bf16 pair
// ---------------------------------------------------------------------------
__global__ __launch_bounds__(256) void convx_kernel(const float* __restrict__ X) {
  size_t i = (size_t)blockIdx.x * blockDim.x + threadIdx.x;
  float4 v = ((const float4*)X)[i];
  __nv_bfloat16 h0 = __float2bfloat16(v.x), h1 = __float2bfloat16(v.y);
  __nv_bfloat16 h2 = __float2bfloat16(v.z), h3 = __float2bfloat16(v.w);
  __nv_bfloat162* hip = (__nv_bfloat162*)g_xhi;
  __nv_bfloat162* lop = (__nv_bfloat162*)g_xlo;
  hip[2*i]   = __nv_bfloat162(h0, h1);
  hip[2*i+1] = __nv_bfloat162(h2, h3);
  lop[2*i]   = __nv_bfloat162(__float2bfloat16(v.x - __bfloat162float(h0)),
                              __float2bfloat16(v.y - __bfloat162float(h1)));
  lop[2*i+1] = __nv_bfloat162(__float2bfloat16(v.z - __bfloat162float(h2)),
                              __float2bfloat16(v.w - __bfloat162float(h3)));
}

// ---------------------------------------------------------------------------
// Prep kernel 2: W[h][d][j] -> Wt[n=h*384+j][d] as (hi, lo) bf16
// ---------------------------------------------------------------------------
__global__ __launch_bounds__(256) void convw_kernel(const float* __restrict__ W) {
  __shared__ float t[32][33];
  int h = blockIdx.z;
  int j0 = blockIdx.x * 32, d0 = blockIdx.y * 32;
  int tx = threadIdx.x & 31, ty = threadIdx.x >> 5;
  const float* Wh = W + (size_t)h * DD * NQKV;
  #pragma unroll
  for (int i = 0; i < 4; i++) {
    int d = d0 + ty + i * 8;
    t[ty + i * 8][tx] = Wh[(size_t)d * NQKV + j0 + tx];
  }
  __syncthreads();
  #pragma unroll
  for (int i = 0; i < 4; i++) {
    int j = j0 + ty + i * 8;
    float v = t[tx][ty + i * 8];
    size_t o = (size_t)(h * NQKV + j) * DD + d0 + tx;
    __nv_bfloat16 hi = __float2bfloat16(v);
    g_wthi[o] = hi;
    g_wtlo[o] = __float2bfloat16(v - __bfloat162float(hi));
  }
}

// ---------------------------------------------------------------------------
// QKV GEMM via mma.sync (bf16x3). Epilogue writes split-bf16 Q/K/V [h][s][e].
// ---------------------------------------------------------------------------
#define BM 128
#define BN 128
#define BK 32
#define NSTAGE_K (DD / BK)

#define ROWB 80
#define TILEB (128 * ROWB)
#define STAGEB (4 * TILEB)
#define GEMM_SMEM (2 * STAGEB)

__global__ __launch_bounds__(256, 1) void qkv_mma_kernel() {
  extern __shared__ char smem[];
  const uint32_t sb = smem_u32(smem);
  const int tid = threadIdx.x;
  const int lane = tid & 31;
  const int wid = tid >> 5;
  const int warp_m = wid >> 2;
  const int warp_n = wid & 3;
  const int m0 = blockIdx.y * BM;
  const int n0 = blockIdx.x * BN;

  float acc[4][4][4];
  #pragma unroll
  for (int i = 0; i < 4; i++)
    #pragma unroll
    for (int j = 0; j < 4; j++)
      #pragma unroll
      for (int q = 0; q < 4; q++) acc[i][j][q] = 0.f;

  const uint32_t a_lrow = (uint32_t)(lane & 15);
  const uint32_t a_lcol = (uint32_t)((lane >> 4) * 16);
  const uint32_t b_lrow = (uint32_t)((lane & 7) + ((lane >> 4) << 3));
  const uint32_t b_lcol = (uint32_t)(((lane >> 3) & 1) * 16);

  auto load_stage = [&](int buf, int c) {
    const int k0 = c * BK;
    const uint32_t sbase = sb + buf * STAGEB;
    #pragma unroll
    for (int i = 0; i < 2; i++) {
      int idx = tid + i * 256;
      int r = idx >> 2, cc = idx & 3;
      uint32_t so = sbase + (uint32_t)(r * ROWB + cc * 16);
      size_t goA = (size_t)(m0 + r) * DD + k0 + cc * 8;
      size_t goB = (size_t)(n0 + r) * DD + k0 + cc * 8;
      CP16(so,              g_xhi  + goA);
      CP16(so + TILEB,      g_xlo  + goA);
      CP16(so + 2 * TILEB,  g_wthi + goB);
      CP16(so + 3 * TILEB,  g_wtlo + goB);
    }
  };

  load_stage(0, 0);
  CP_COMMIT();

  for (int c = 0; c < NSTAGE_K; c++) {
    if (c + 1 < NSTAGE_K) {
      load_stage((c + 1) & 1, c + 1);
      CP_COMMIT();
      CP_WAIT(1);
    } else {
      CP_WAIT(0);
    }
    __syncthreads();

    const uint32_t sbase = sb + (c & 1) * STAGEB;
    const uint32_t sAh = sbase;
    const uint32_t sAl = sbase + TILEB;
    const uint32_t sBh = sbase + 2 * TILEB;
    const uint32_t sBl = sbase + 3 * TILEB;

    #pragma unroll
    for (int ks = 0; ks < 2; ks++) {
      const uint32_t kb = (uint32_t)(ks * 32);
      uint32_t ah[4][4], al[4][4];
      #pragma unroll
      for (int mt = 0; mt < 4; mt++) {
        uint32_t row0 = (uint32_t)(warp_m * 64 + mt * 16);
        uint32_t off = (row0 + a_lrow) * ROWB + kb + a_lcol;
        LDSM_X4(ah[mt], sAh + off);
        LDSM_X4(al[mt], sAl + off);
      }
      uint32_t bh[4][2], bl[4][2];
      #pragma unroll
      for (int np = 0; np < 2; np++) {
        uint32_t nrow0 = (uint32_t)(warp_n * 32 + np * 16);
        uint32_t off = (nrow0 + b_lrow) * ROWB + kb + b_lcol;
        uint32_t q[4];
        LDSM_X4(q, sBh + off);
        bh[2*np][0] = q[0]; bh[2*np][1] = q[1];
        bh[2*np+1][0] = q[2]; bh[2*np+1][1] = q[3];
        LDSM_X4(q, sBl + off);
        bl[2*np][0] = q[0]; bl[2*np][1] = q[1];
        bl[2*np+1][0] = q[2]; bl[2*np+1][1] = q[3];
      }
      #pragma unroll
      for (int mt = 0; mt < 4; mt++) {
        #pragma unroll
        for (int nt = 0; nt < 4; nt++) {
          mma16816(acc[mt][nt], ah[mt], bh[nt]);
          mma16816(acc[mt][nt], ah[mt], bl[nt]);
          mma16816(acc[mt][nt], al[mt], bh[nt]);
        }
      }
    }
    __syncthreads();
  }

  // Epilogue: write split-bf16 into g_{q,k,v}{hi,lo}[h][s][e]
  const int g = lane >> 2, tig = lane & 3;
  const int h   = n0 / NQKV;
  const int part = (n0 % NQKV) / EE;           // 0=Q 1=K 2=V
  __nv_bfloat16* dhi = (part == 0) ? g_qhi : (part == 1) ? g_khi : g_vhi;
  __nv_bfloat16* dlo = (part == 0) ? g_qlo : (part == 1) ? g_klo : g_vlo;
  const float scl = (part == 0) ? SCALE : 1.0f;

  #pragma unroll
  for (int mt = 0; mt < 4; mt++) {
    int row = m0 + warp_m * 64 + mt * 16 + g;
    #pragma unroll
    for (int nt = 0; nt < 4; nt++) {
      int col = warp_n * 32 + nt * 8 + tig * 2;
      #pragma unroll
      for (int half = 0; half < 2; half++) {
        int r = row + half * 8;
        float v0 = acc[mt][nt][2*half]     * scl;
        float v1 = acc[mt][nt][2*half + 1] * scl;
        float h0, l0, h1, l1;
        splitf(v0, h0, l0);
        splitf(v1, h1, l1);
        size_t base = ((size_t)h * SS + r) * EE + col;
        *(uint32_t*)&dhi[base] = pack2(h0, h1);
        *(uint32_t*)&dlo[base] = pack2(l0, l1);
      }
    }
  }
}

// ---------------------------------------------------------------------------
// Flash attention on mma.sync, bf16x3 split precision.
// Block: 128 q-rows x 1 head. 8 warps x 16 rows. KV tiles of 64, cp.async x2.
// ---------------------------------------------------------------------------
#define AQ  128
#define AKV 64
#define NKV (SS / AKV)        // 32
#define AROWB 272             // 256B data + 16B pad (stride/16 = 17, odd)

#define SQH 0
#define SQL (AQ * AROWB)                  // 34816
#define SST (2 * AQ * AROWB)              // 69632
#define KVT (AKV * AROWB)                 // 17408
#define STAGE (4 * KVT)                   // 69632
#define ATT_SMEM (SST + 2 * STAGE)        // 208896

__global__ __launch_bounds__(256, 1) void attn_mma_kernel(float* __restrict__ out) {
  extern __shared__ char smem[];
  const uint32_t sb = smem_u32(smem);
  const int tid  = threadIdx.x;
  const int lane = tid & 31;
  const int warp = tid >> 5;
  const int h  = blockIdx.y;
  const int q0 = blockIdx.x * AQ;

  const __nv_bfloat16* qh = g_qhi + ((size_t)h * SS + q0) * EE;
  const __nv_bfloat16* ql = g_qlo + ((size_t)h * SS + q0) * EE;
  const __nv_bfloat16* kh = g_khi + (size_t)h * SS * EE;
  const __nv_bfloat16* kl = g_klo + (size_t)h * SS * EE;
  const __nv_bfloat16* vh = g_vhi + (size_t)h * SS * EE;
  const __nv_bfloat16* vl = g_vlo + (size_t)h * SS * EE;

  // Q tile -> smem (plain vector copies, once)
  #pragma unroll
  for (int i = 0; i < 8; i++) {
    int idx = tid + i * 256;            // 0..2047
    int r = idx >> 4, cc = idx & 15;
    uint32_t so = (uint32_t)(r * AROWB + cc * 16);
    *(uint4*)(smem + SQH + so) = *(const uint4*)(qh + (size_t)r * EE + cc * 8);
    *(uint4*)(smem + SQL + so) = *(const uint4*)(ql + (size_t)r * EE + cc * 8);
  }

  auto load_kv = [&](int buf, int t) {
    const int kv0 = t * AKV;
    const uint32_t sbase = sb + SST + buf * STAGE;
    #pragma unroll
    for (int i = 0; i < 4; i++) {
      int idx = tid + i * 256;          // 0..1023
      int r = idx >> 4, cc = idx & 15;
      uint32_t so = sbase + (uint32_t)(r * AROWB + cc * 16);
      size_t go = (size_t)(kv0 + r) * EE + cc * 8;
      CP16(so,           kh + go);
      CP16(so + KVT,     kl + go);
      CP16(so + 2*KVT,   vh + go);
      CP16(so + 3*KVT,   vl + go);
    }
  };

  load_kv(0, 0);
  CP_COMMIT();

  // fragment lane geometry
  const int g   = lane >> 2;
  const int tig = lane & 3;
  const uint32_t a_lrow = (uint32_t)(lane & 15);
  const uint32_t a_lcol = (uint32_t)((lane >> 4) * 16);
  const uint32_t b_lrow = (uint32_t)((lane & 7) + ((lane >> 4) << 3));
  const uint32_t b_lcol = (uint32_t)(((lane >> 3) & 1) * 16);
  // trans-ldmatrix (V) lane geometry
  const uint32_t v_row  = (uint32_t)((lane & 7) + (((lane >> 3) & 1) << 3));
  const uint32_t v_colb = (uint32_t)(((lane >> 4) * 8) * 2);

  float m0 = -INFINITY, m1 = -INFINITY, l0 = 0.f, l1 = 0.f;
  float oacc[16][4];
  #pragma unroll
  for (int i = 0; i < 16; i++)
    #pragma unroll
    for (int j = 0; j < 4; j++) oacc[i][j] = 0.f;

  for (int t = 0; t < NKV; t++) {
    if (t + 1 < NKV) {
      load_kv((t + 1) & 1, t + 1);
      CP_COMMIT();
      CP_WAIT(1);
    } else {
      CP_WAIT(0);
    }
    __syncthreads();

    const uint32_t sK  = sb + SST + (t & 1) * STAGE;
    const uint32_t sKl = sK + KVT;
    const uint32_t sV  = sK + 2 * KVT;
    const uint32_t sVl = sK + 3 * KVT;

    // ---- S = Q K^T (3-way split) ----
    float sacc[8][4];
    #pragma unroll
    for (int i = 0; i < 8; i++)
      #pragma unroll
      for (int j = 0; j < 4; j++) sacc[i][j] = 0.f;

    #pragma unroll
    for (int ks = 0; ks < 8; ks++) {
      const uint32_t kb = (uint32_t)(ks * 32);
      uint32_t ah[4], al[4];
      uint32_t qoff = (uint32_t)(warp * 16 + a_lrow) * AROWB + kb + a_lcol;
      LDSM_X4(ah, sb + SQH + qoff);
      LDSM_X4(al, sb + SQL + qoff);
      #pragma unroll
      for (int np = 0; np < 4; np++) {
        uint32_t koff = (uint32_t)(np * 16 + b_lrow) * AROWB + kb + b_lcol;
        uint32_t h4[4], l4[4];
        LDSM_X4(h4, sK  + koff);
        LDSM_X4(l4, sKl + koff);
        uint32_t bh0[2] = {h4[0], h4[1]}, bh1[2] = {h4[2], h4[3]};
        uint32_t bl0[2] = {l4[0], l4[1]}, bl1[2] = {l4[2], l4[3]};
        mma16816(sacc[2*np],   ah, bh0);
        mma16816(sacc[2*np],   ah, bl0);
        mma16816(sacc[2*np],   al, bh0);
        mma16816(sacc[2*np+1], ah, bh1);
        mma16816(sacc[2*np+1], ah, bl1);
        mma16816(sacc[2*np+1], al, bh1);
      }
    }

    // ---- online softmax (rows g and g+8 of this warp) ----
    float r0 = -INFINITY, r1 = -INFINITY;
    #pragma unroll
    for (int i = 0; i < 8; i++) {
      r0 = fmaxf(r0, fmaxf(sacc[i][0], sacc[i][1]));
      r1 = fmaxf(r1, fmaxf(sacc[i][2], sacc[i][3]));
    }
    r0 = fmaxf(r0, __shfl_xor_sync(0xffffffffu, r0, 1));
    r0 = fmaxf(r0, __shfl_xor_sync(0xffffffffu, r0, 2));
    r1 = fmaxf(r1, __shfl_xor_sync(0xffffffffu, r1, 1));
    r1 = fmaxf(r1, __shfl_xor_sync(0xffffffffu, r1, 2));

    float mn0 = fmaxf(m0, r0), mn1 = fmaxf(m1, r1);
    float al0 = __expf(m0 - mn0), al1 = __expf(m1 - mn1);
    m0 = mn0; m1 = mn1;

    float ps0 = 0.f, ps1 = 0.f;
    #pragma unroll
    for (int i = 0; i < 8; i++) {
      sacc[i][0] = __expf(sacc[i][0] - mn0);
      sacc[i][1] = __expf(sacc[i][1] - mn0);
      sacc[i][2] = __expf(sacc[i][2] - mn1);
      sacc[i][3] = __expf(sacc[i][3] - mn1);
      ps0 += sacc[i][0] + sacc[i][1];
      ps1 += sacc[i][2] + sacc[i][3];
    }
    ps0 += __shfl_xor_sync(0xffffffffu, ps0, 1);
    ps0 += __shfl_xor_sync(0xffffffffu, ps0, 2);
    ps1 += __shfl_xor_sync(0xffffffffu, ps1, 1);
    ps1 += __shfl_xor_sync(0xffffffffu, ps1, 2);
    l0 = l0 * al0 + ps0;
    l1 = l1 * al1 + ps1;

    #pragma unroll
    for (int i = 0; i < 16; i++) {
      oacc[i][0] *= al0; oacc[i][1] *= al0;
      oacc[i][2] *= al1; oacc[i][3] *= al1;
    }

    // ---- O += P V (3-way split), 4 k16 steps over kv ----
    #pragma unroll
    for (int j = 0; j < 4; j++) {
      // P a-fragments from S tiles 2j, 2j+1 (register relayout)
      float h00, q00, h01, q01, h02, q02, h03, q03;
      float h10, q10, h11, q11, h12, q12, h13, q13;
      splitf(sacc[2*j][0],   h00, q00); splitf(sacc[2*j][1],   h01, q01);
      splitf(sacc[2*j][2],   h02, q02); splitf(sacc[2*j][3],   h03, q03);
      splitf(sacc[2*j+1][0], h10, q10); splitf(sacc[2*j+1][1], h11, q11);
      splitf(sacc[2*j+1][2], h12, q12); splitf(sacc[2*j+1][3], h13, q13);
      uint32_t ph[4], pl[4];
      ph[0] = pack2(h00, h01); ph[1] = pack2(h02, h03);
      ph[2] = pack2(h10, h11); ph[3] = pack2(h12, h13);
      pl[0] = pack2(q00, q01); pl[1] = pack2(q02, q03);
      pl[2] = pack2(q10, q11); pl[3] = pack2(q12, q13);

      #pragma unroll
      for (int ep = 0; ep < 8; ep++) {
        uint32_t voff = (uint32_t)(j * 16 + v_row) * AROWB + (uint32_t)(ep * 32) + v_colb;
        uint32_t h4[4], l4[4];
        LDSM_X4_T(h4, sV  + voff);
        LDSM_X4_T(l4, sVl + voff);
        uint32_t bh0[2] = {h4[0], h4[1]}, bh1[2] = {h4[2], h4[3]};
        uint32_t bl0[2] = {l4[0], l4[1]}, bl1[2] = {l4[2], l4[3]};
        mma16816(oacc[2*ep],   ph, bh0);
        mma16816(oacc[2*ep],   ph, bl0);
        mma16816(oacc[2*ep],   pl, bh0);
        mma16816(oacc[2*ep+1], ph, bh1);
        mma16816(oacc[2*ep+1], ph, bl1);
        mma16816(oacc[2*ep+1], pl, bh1);
      }
    }
    __syncthreads();
  }

  // ---- normalize + write out[s][h*128+e] ----
  const float i0 = 1.f / l0, i1 = 1.f / l1;
  const int row0 = q0 + warp * 16 + g;
  #pragma unroll
  for (int et = 0; et < 16; et++) {
    int col = h * EE + et * 8 + tig * 2;
    *(float2*)&out[(size_t)row0 * (HH*EE) + col] =
        make_float2(oacc[et][0] * i0, oacc[et][1] * i0);
    *(float2*)&out[(size_t)(row0 + 8) * (HH*EE) + col] =
        make_float2(oacc[et][2] * i1, oacc[et][3] * i1);
  }
}

// ---------------------------------------------------------------------------
extern "C" void kernel_launch(void* const* d_in, const int* in_sizes, int n_in,
                              void* d_out, int out_size) {
  const float* x = (const float*)d_in[0];     // [2048, 2048]
  const float* w = (const float*)d_in[1];     // [16, 2048, 384]
  float* out = (float*)d_out;                 // [2048, 2048]
  (void)in_sizes; (void)n_in; (void)out_size;

  cudaFuncSetAttribute(qkv_mma_kernel,
                       cudaFuncAttributeMaxDynamicSharedMemorySize, GEMM_SMEM);
  cudaFuncSetAttribute(attn_mma_kernel,
                       cudaFuncAttributeMaxDynamicSharedMemorySize, ATT_SMEM);

  convx_kernel<<<(SS * DD / 4) / 256, 256>>>(x);
  convw_kernel<<<dim3(NQKV / 32, DD / 32, HH), 256>>>(w);

  qkv_mma_kernel<<<dim3(NTOT / BN, SS / BM), 256, GEMM_SMEM>>>();

  attn_mma_kernel<<<dim3(SS / AQ, HH), 256, ATT_SMEM>>>(out);
}

// round 5
// speedup vs baseline: 3.4923x; 1.0613x over previous
#include <cuda_runtime.h>
#include <cuda_bf16.h>
#include <math.h>
#include <stdint.h>

#define SS 2048
#define DD 2048
#define HH 16
#define EE 128
#define NQKV (3*EE)        // 384
#define NTOT (HH*NQKV)     // 6144
#define SCALE 0.08838834764831845f

// ---------------------------------------------------------------------------
// Device scratch (static — no runtime allocation allowed)
// ---------------------------------------------------------------------------
__device__ __nv_bfloat16 g_xhi[(size_t)SS * DD];
__device__ __nv_bfloat16 g_xlo[(size_t)SS * DD];
__device__ __nv_bfloat16 g_wthi[(size_t)NTOT * DD];
__device__ __nv_bfloat16 g_wtlo[(size_t)NTOT * DD];
// Projected Q/K/V, split bf16, layout [h][s][e]  (Q pre-scaled by 1/sqrt(E))
__device__ __nv_bfloat16 g_qhi[(size_t)HH * SS * EE];
__device__ __nv_bfloat16 g_qlo[(size_t)HH * SS * EE];
__device__ __nv_bfloat16 g_khi[(size_t)HH * SS * EE];
__device__ __nv_bfloat16 g_klo[(size_t)HH * SS * EE];
__device__ __nv_bfloat16 g_vhi[(size_t)HH * SS * EE];
__device__ __nv_bfloat16 g_vlo[(size_t)HH * SS * EE];

// ---------------------------------------------------------------------------
// PTX helpers (base-target-safe)
// ---------------------------------------------------------------------------
__device__ __forceinline__ uint32_t smem_u32(const void* p) {
  uint32_t a;
  asm("{ .reg .u64 t; cvta.to.shared.u64 t, %1; cvt.u32.u64 %0, t; }"
      : "=r"(a) : "l"(p));
  return a;
}

#define LDSM_X4(r, a)                                                        \
  asm volatile("ldmatrix.sync.aligned.m8n8.x4.shared.b16 {%0,%1,%2,%3}, [%4];" \
               : "=r"((r)[0]), "=r"((r)[1]), "=r"((r)[2]), "=r"((r)[3])      \
               : "r"(a))

#define LDSM_X4_T(r, a)                                                      \
  asm volatile("ldmatrix.sync.aligned.m8n8.x4.trans.shared.b16 {%0,%1,%2,%3}, [%4];" \
               : "=r"((r)[0]), "=r"((r)[1]), "=r"((r)[2]), "=r"((r)[3])      \
               : "r"(a))

__device__ __forceinline__ void mma16816(float* c, const uint32_t* a,
                                         const uint32_t* b) {
  asm volatile(
      "mma.sync.aligned.m16n8k16.row.col.f32.bf16.bf16.f32 "
      "{%0,%1,%2,%3}, {%4,%5,%6,%7}, {%8,%9}, {%0,%1,%2,%3};"
      : "+f"(c[0]), "+f"(c[1]), "+f"(c[2]), "+f"(c[3])
      : "r"(a[0]), "r"(a[1]), "r"(a[2]), "r"(a[3]), "r"(b[0]), "r"(b[1]));
}

#define CP16(sm, gp)                                                   \
  asm volatile("cp.async.cg.shared.global [%0], [%1], 16;" ::          \
               "r"(sm), "l"(gp))
#define CP_COMMIT() asm volatile("cp.async.commit_group;" ::: "memory")
#define CP_WAIT(n)  asm volatile("cp.async.wait_group %0;" :: "n"(n) : "memory")

__device__ __forceinline__ void splitf(float v, float& hf, float& lf) {
  __nv_bfloat16 h = __float2bfloat16(v);
  hf = __bfloat162float(h);
  lf = v - hf;
}
__device__ __forceinline__ uint32_t pack2(float a, float b) {
  __nv_bfloat162 t = __floats2bfloat162_rn(a, b);
  return *(uint32_t*)&t;
}

// ---------------------------------------------------------------------------
// Prep kernel 1: X fp32 -> (hi, lo) bf16 pair
// ---------------------------------------------------------------------------
__global__ __launch_bounds__(256) void convx_kernel(const float* __restrict__ X) {
  size_t i = (size_t)blockIdx.x * blockDim.x + threadIdx.x;
  float4 v = ((const float4*)X)[i];
  __nv_bfloat16 h0 = __float2bfloat16(v.x), h1 = __float2bfloat16(v.y);
  __nv_bfloat16 h2 = __float2bfloat16(v.z), h3 = __float2bfloat16(v.w);
  __nv_bfloat162* hip = (__nv_bfloat162*)g_xhi;
  __nv_bfloat162* lop = (__nv_bfloat162*)g_xlo;
  hip[2*i]   = __nv_bfloat162(h0, h1);
  hip[2*i+1] = __nv_bfloat162(h2, h3);
  lop[2*i]   = __nv_bfloat162(__float2bfloat16(v.x - __bfloat162float(h0)),
                              __float2bfloat16(v.y - __bfloat162float(h1)));
  lop[2*i+1] = __nv_bfloat162(__float2bfloat16(v.z - __bfloat162float(h2)),
                              __float2bfloat16(v.w - __bfloat162float(h3)));
}

// ---------------------------------------------------------------------------
// Prep kernel 2: W[h][d][j] -> Wt[n=h*384+j][d] as (hi, lo) bf16
// ---------------------------------------------------------------------------
__global__ __launch_bounds__(256) void convw_kernel(const float* __restrict__ W) {
  __shared__ float t[32][33];
  int h = blockIdx.z;
  int j0 = blockIdx.x * 32, d0 = blockIdx.y * 32;
  int tx = threadIdx.x & 31, ty = threadIdx.x >> 5;
  const float* Wh = W + (size_t)h * DD * NQKV;
  #pragma unroll
  for (int i = 0; i < 4; i++) {
    int d = d0 + ty + i * 8;
    t[ty + i * 8][tx] = Wh[(size_t)d * NQKV + j0 + tx];
  }
  __syncthreads();
  #pragma unroll
  for (int i = 0; i < 4; i++) {
    int j = j0 + ty + i * 8;
    float v = t[tx][ty + i * 8];
    size_t o = (size_t)(h * NQKV + j) * DD + d0 + tx;
    __nv_bfloat16 hi = __float2bfloat16(v);
    g_wthi[o] = hi;
    g_wtlo[o] = __float2bfloat16(v - __bfloat162float(hi));
  }
}

// ---------------------------------------------------------------------------
// QKV GEMM via mma.sync (bf16x3). 512 threads, BM=256, BN=128, BK=32.
// 16 warps in 4m x 4n grid, warp tile 64x32. Single sync per k-iteration.
// ---------------------------------------------------------------------------
#define BM 256
#define BN 128
#define BK 32
#define NSTAGE_K (DD / BK)          // 64

#define ROWB 80                     // 64B data + 16B pad
#define TILE_A (BM * ROWB)          // 20480
#define TILE_B (BN * ROWB)          // 10240
#define STAGEB (2 * TILE_A + 2 * TILE_B)   // 61440
#define GEMM_SMEM (2 * STAGEB)             // 122880

__global__ __launch_bounds__(512, 1) void qkv_mma_kernel() {
  extern __shared__ char smem[];
  const uint32_t sb = smem_u32(smem);
  const int tid = threadIdx.x;
  const int lane = tid & 31;
  const int wid = tid >> 5;
  const int warp_m = wid >> 2;           // 0..3
  const int warp_n = wid & 3;            // 0..3
  const int m0 = blockIdx.y * BM;
  const int n0 = blockIdx.x * BN;

  float acc[4][4][4];
  #pragma unroll
  for (int i = 0; i < 4; i++)
    #pragma unroll
    for (int j = 0; j < 4; j++)
      #pragma unroll
      for (int q = 0; q < 4; q++) acc[i][j][q] = 0.f;

  const uint32_t a_lrow = (uint32_t)(lane & 15);
  const uint32_t a_lcol = (uint32_t)((lane >> 4) * 16);
  const uint32_t b_lrow = (uint32_t)((lane & 7) + ((lane >> 4) << 3));
  const uint32_t b_lcol = (uint32_t)(((lane >> 3) & 1) * 16);

  auto load_stage = [&](int buf, int c) {
    const int k0 = c * BK;
    const uint32_t sbase = sb + buf * STAGEB;
    // A hi/lo: 1024 chunks each (256 rows x 4)
    #pragma unroll
    for (int i = 0; i < 2; i++) {
      int idx = tid + i * 512;
      int r = idx >> 2, cc = idx & 3;
      uint32_t so = sbase + (uint32_t)(r * ROWB + cc * 16);
      size_t goA = (size_t)(m0 + r) * DD + k0 + cc * 8;
      CP16(so,          g_xhi + goA);
      CP16(so + TILE_A, g_xlo + goA);
    }
    // B hi/lo: 512 chunks each (128 rows x 4)
    {
      int r = tid >> 2, cc = tid & 3;
      uint32_t so = sbase + 2 * TILE_A + (uint32_t)(r * ROWB + cc * 16);
      size_t goB = (size_t)(n0 + r) * DD + k0 + cc * 8;
      CP16(so,          g_wthi + goB);
      CP16(so + TILE_B, g_wtlo + goB);
    }
  };

  load_stage(0, 0);
  CP_COMMIT();

  for (int c = 0; c < NSTAGE_K; c++) {
    CP_WAIT(0);
    __syncthreads();
    if (c + 1 < NSTAGE_K) {
      load_stage((c + 1) & 1, c + 1);
      CP_COMMIT();
    }

    const uint32_t sbase = sb + (c & 1) * STAGEB;
    const uint32_t sAh = sbase;
    const uint32_t sAl = sbase + TILE_A;
    const uint32_t sBh = sbase + 2 * TILE_A;
    const uint32_t sBl = sbase + 2 * TILE_A + TILE_B;

    #pragma unroll
    for (int ks = 0; ks < 2; ks++) {
      const uint32_t kb = (uint32_t)(ks * 32);
      uint32_t ah[4][4], al[4][4];
      #pragma unroll
      for (int mt = 0; mt < 4; mt++) {
        uint32_t row0 = (uint32_t)(warp_m * 64 + mt * 16);
        uint32_t off = (row0 + a_lrow) * ROWB + kb + a_lcol;
        LDSM_X4(ah[mt], sAh + off);
        LDSM_X4(al[mt], sAl + off);
      }
      uint32_t bh[4][2], bl[4][2];
      #pragma unroll
      for (int np = 0; np < 2; np++) {
        uint32_t nrow0 = (uint32_t)(warp_n * 32 + np * 16);
        uint32_t off = (nrow0 + b_lrow) * ROWB + kb + b_lcol;
        uint32_t q[4];
        LDSM_X4(q, sBh + off);
        bh[2*np][0] = q[0]; bh[2*np][1] = q[1];
        bh[2*np+1][0] = q[2]; bh[2*np+1][1] = q[3];
        LDSM_X4(q, sBl + off);
        bl[2*np][0] = q[0]; bl[2*np][1] = q[1];
        bl[2*np+1][0] = q[2]; bl[2*np+1][1] = q[3];
      }
      #pragma unroll
      for (int mt = 0; mt < 4; mt++) {
        #pragma unroll
        for (int nt = 0; nt < 4; nt++) {
          mma16816(acc[mt][nt], ah[mt], bh[nt]);
          mma16816(acc[mt][nt], ah[mt], bl[nt]);
          mma16816(acc[mt][nt], al[mt], bh[nt]);
        }
      }
    }
    __syncthreads();
  }

  // Epilogue: write split-bf16 into g_{q,k,v}{hi,lo}[h][s][e]
  const int g = lane >> 2, tig = lane & 3;
  const int h    = n0 / NQKV;
  const int part = (n0 % NQKV) / EE;           // 0=Q 1=K 2=V
  __nv_bfloat16* dhi = (part == 0) ? g_qhi : (part == 1) ? g_khi : g_vhi;
  __nv_bfloat16* dlo = (part == 0) ? g_qlo : (part == 1) ? g_klo : g_vlo;
  const float scl = (part == 0) ? SCALE : 1.0f;

  #pragma unroll
  for (int mt = 0; mt < 4; mt++) {
    int row = m0 + warp_m * 64 + mt * 16 + g;
    #pragma unroll
    for (int nt = 0; nt < 4; nt++) {
      int col = warp_n * 32 + nt * 8 + tig * 2;
      #pragma unroll
      for (int half = 0; half < 2; half++) {
        int r = row + half * 8;
        float v0 = acc[mt][nt][2*half]     * scl;
        float v1 = acc[mt][nt][2*half + 1] * scl;
        float h0, l0, h1, l1;
        splitf(v0, h0, l0);
        splitf(v1, h1, l1);
        size_t base = ((size_t)h * SS + r) * EE + col;
        *(uint32_t*)&dhi[base] = pack2(h0, h1);
        *(uint32_t*)&dlo[base] = pack2(l0, l1);
      }
    }
  }
}

// ---------------------------------------------------------------------------
// Flash attention on mma.sync, bf16x3 split. 128 q-rows x head, 8 warps.
// KV tiles of 64, cp.async double buffer, single sync per tile.
// ---------------------------------------------------------------------------
#define AQ  128
#define AKV 64
#define NKV (SS / AKV)        // 32
#define AROWB 272             // 256B data + 16B pad

#define SQH 0
#define SQL (AQ * AROWB)
#define SST (2 * AQ * AROWB)              // 69632
#define KVT (AKV * AROWB)                 // 17408
#define STAGE (4 * KVT)                   // 69632
#define ATT_SMEM (SST + 2 * STAGE)        // 208896

__global__ __launch_bounds__(256, 1) void attn_mma_kernel(float* __restrict__ out) {
  extern __shared__ char smem[];
  const uint32_t sb = smem_u32(smem);
  const int tid  = threadIdx.x;
  const int lane = tid & 31;
  const int warp = tid >> 5;
  const int h  = blockIdx.y;
  const int q0 = blockIdx.x * AQ;

  const __nv_bfloat16* qh = g_qhi + ((size_t)h * SS + q0) * EE;
  const __nv_bfloat16* ql = g_qlo + ((size_t)h * SS + q0) * EE;
  const __nv_bfloat16* kh = g_khi + (size_t)h * SS * EE;
  const __nv_bfloat16* kl = g_klo + (size_t)h * SS * EE;
  const __nv_bfloat16* vh = g_vhi + (size_t)h * SS * EE;
  const __nv_bfloat16* vl = g_vlo + (size_t)h * SS * EE;

  #pragma unroll
  for (int i = 0; i < 8; i++) {
    int idx = tid + i * 256;
    int r = idx >> 4, cc = idx & 15;
    uint32_t so = (uint32_t)(r * AROWB + cc * 16);
    *(uint4*)(smem + SQH + so) = *(const uint4*)(qh + (size_t)r * EE + cc * 8);
    *(uint4*)(smem + SQL + so) = *(const uint4*)(ql + (size_t)r * EE + cc * 8);
  }

  auto load_kv = [&](int buf, int t) {
    const int kv0 = t * AKV;
    const uint32_t sbase = sb + SST + buf * STAGE;
    #pragma unroll
    for (int i = 0; i < 4; i++) {
      int idx = tid + i * 256;
      int r = idx >> 4, cc = idx & 15;
      uint32_t so = sbase + (uint32_t)(r * AROWB + cc * 16);
      size_t go = (size_t)(kv0 + r) * EE + cc * 8;
      CP16(so,           kh + go);
      CP16(so + KVT,     kl + go);
      CP16(so + 2*KVT,   vh + go);
      CP16(so + 3*KVT,   vl + go);
    }
  };

  load_kv(0, 0);
  CP_COMMIT();

  const int g   = lane >> 2;
  const int tig = lane & 3;
  const uint32_t a_lrow = (uint32_t)(lane & 15);
  const uint32_t a_lcol = (uint32_t)((lane >> 4) * 16);
  const uint32_t b_lrow = (uint32_t)((lane & 7) + ((lane >> 4) << 3));
  const uint32_t b_lcol = (uint32_t)(((lane >> 3) & 1) * 16);
  const uint32_t v_row  = (uint32_t)((lane & 7) + (((lane >> 3) & 1) << 3));
  const uint32_t v_colb = (uint32_t)(((lane >> 4) * 8) * 2);

  float m0 = -INFINITY, m1 = -INFINITY, l0 = 0.f, l1 = 0.f;
  float oacc[16][4];
  #pragma unroll
  for (int i = 0; i < 16; i++)
    #pragma unroll
    for (int j = 0; j < 4; j++) oacc[i][j] = 0.f;

  for (int t = 0; t < NKV; t++) {
    CP_WAIT(0);
    __syncthreads();
    if (t + 1 < NKV) {
      load_kv((t + 1) & 1, t + 1);
      CP_COMMIT();
    }

    const uint32_t sK  = sb + SST + (t & 1) * STAGE;
    const uint32_t sKl = sK + KVT;
    const uint32_t sV  = sK + 2 * KVT;
    const uint32_t sVl = sK + 3 * KVT;

    // ---- S = Q K^T (3-way split) ----
    float sacc[8][4];
    #pragma unroll
    for (int i = 0; i < 8; i++)
      #pragma unroll
      for (int j = 0; j < 4; j++) sacc[i][j] = 0.f;

    #pragma unroll
    for (int ks = 0; ks < 8; ks++) {
      const uint32_t kb = (uint32_t)(ks * 32);
      uint32_t ah[4], al[4];
      uint32_t qoff = (uint32_t)(warp * 16 + a_lrow) * AROWB + kb + a_lcol;
      LDSM_X4(ah, sb + SQH + qoff);
      LDSM_X4(al, sb + SQL + qoff);
      #pragma unroll
      for (int np = 0; np < 4; np++) {
        uint32_t koff = (uint32_t)(np * 16 + b_lrow) * AROWB + kb + b_lcol;
        uint32_t h4[4], l4[4];
        LDSM_X4(h4, sK  + koff);
        LDSM_X4(l4, sKl + koff);
        uint32_t bh0[2] = {h4[0], h4[1]}, bh1[2] = {h4[2], h4[3]};
        uint32_t bl0[2] = {l4[0], l4[1]}, bl1[2] = {l4[2], l4[3]};
        mma16816(sacc[2*np],   ah, bh0);
        mma16816(sacc[2*np],   ah, bl0);
        mma16816(sacc[2*np],   al, bh0);
        mma16816(sacc[2*np+1], ah, bh1);
        mma16816(sacc[2*np+1], ah, bl1);
        mma16816(sacc[2*np+1], al, bh1);
      }
    }

    // ---- online softmax ----
    float r0 = -INFINITY, r1 = -INFINITY;
    #pragma unroll
    for (int i = 0; i < 8; i++) {
      r0 = fmaxf(r0, fmaxf(sacc[i][0], sacc[i][1]));
      r1 = fmaxf(r1, fmaxf(sacc[i][2], sacc[i][3]));
    }
    r0 = fmaxf(r0, __shfl_xor_sync(0xffffffffu, r0, 1));
    r0 = fmaxf(r0, __shfl_xor_sync(0xffffffffu, r0, 2));
    r1 = fmaxf(r1, __shfl_xor_sync(0xffffffffu, r1, 1));
    r1 = fmaxf(r1, __shfl_xor_sync(0xffffffffu, r1, 2));

    float mn0 = fmaxf(m0, r0), mn1 = fmaxf(m1, r1);
    float al0 = __expf(m0 - mn0), al1 = __expf(m1 - mn1);
    m0 = mn0; m1 = mn1;

    float ps0 = 0.f, ps1 = 0.f;
    #pragma unroll
    for (int i = 0; i < 8; i++) {
      sacc[i][0] = __expf(sacc[i][0] - mn0);
      sacc[i][1] = __expf(sacc[i][1] - mn0);
      sacc[i][2] = __expf(sacc[i][2] - mn1);
      sacc[i][3] = __expf(sacc[i][3] - mn1);
      ps0 += sacc[i][0] + sacc[i][1];
      ps1 += sacc[i][2] + sacc[i][3];
    }
    ps0 += __shfl_xor_sync(0xffffffffu, ps0, 1);
    ps0 += __shfl_xor_sync(0xffffffffu, ps0, 2);
    ps1 += __shfl_xor_sync(0xffffffffu, ps1, 1);
    ps1 += __shfl_xor_sync(0xffffffffu, ps1, 2);
    l0 = l0 * al0 + ps0;
    l1 = l1 * al1 + ps1;

    #pragma unroll
    for (int i = 0; i < 16; i++) {
      oacc[i][0] *= al0; oacc[i][1] *= al0;
      oacc[i][2] *= al1; oacc[i][3] *= al1;
    }

    // ---- O += P V (3-way split) ----
    #pragma unroll
    for (int j = 0; j < 4; j++) {
      float h00, q00, h01, q01, h02, q02, h03, q03;
      float h10, q10, h11, q11, h12, q12, h13, q13;
      splitf(sacc[2*j][0],   h00, q00); splitf(sacc[2*j][1],   h01, q01);
      splitf(sacc[2*j][2],   h02, q02); splitf(sacc[2*j][3],   h03, q03);
      splitf(sacc[2*j+1][0], h10, q10); splitf(sacc[2*j+1][1], h11, q11);
      splitf(sacc[2*j+1][2], h12, q12); splitf(sacc[2*j+1][3], h13, q13);
      uint32_t ph[4], pl[4];
      ph[0] = pack2(h00, h01); ph[1] = pack2(h02, h03);
      ph[2] = pack2(h10, h11); ph[3] = pack2(h12, h13);
      pl[0] = pack2(q00, q01); pl[1] = pack2(q02, q03);
      pl[2] = pack2(q10, q11); pl[3] = pack2(q12, q13);

      #pragma unroll
      for (int ep = 0; ep < 8; ep++) {
        uint32_t voff = (uint32_t)(j * 16 + v_row) * AROWB + (uint32_t)(ep * 32) + v_colb;
        uint32_t h4[4], l4[4];
        LDSM_X4_T(h4, sV  + voff);
        LDSM_X4_T(l4, sVl + voff);
        uint32_t bh0[2] = {h4[0], h4[1]}, bh1[2] = {h4[2], h4[3]};
        uint32_t bl0[2] = {l4[0], l4[1]}, bl1[2] = {l4[2], l4[3]};
        mma16816(oacc[2*ep],   ph, bh0);
        mma16816(oacc[2*ep],   ph, bl0);
        mma16816(oacc[2*ep],   pl, bh0);
        mma16816(oacc[2*ep+1], ph, bh1);
        mma16816(oacc[2*ep+1], ph, bl1);
        mma16816(oacc[2*ep+1], pl, bh1);
      }
    }
  }

  // ---- normalize + write ----
  const float i0 = 1.f / l0, i1 = 1.f / l1;
  const int row0 = q0 + warp * 16 + g;
  #pragma unroll
  for (int et = 0; et < 16; et++) {
    int col = h * EE + et * 8 + tig * 2;
    *(float2*)&out[(size_t)row0 * (HH*EE) + col] =
        make_float2(oacc[et][0] * i0, oacc[et][1] * i0);
    *(float2*)&out[(size_t)(row0 + 8) * (HH*EE) + col] =
        make_float2(oacc[et][2] * i1, oacc[et][3] * i1);
  }
}

// ---------------------------------------------------------------------------
extern "C" void kernel_launch(void* const* d_in, const int* in_sizes, int n_in,
                              void* d_out, int out_size) {
  const float* x = (const float*)d_in[0];     // [2048, 2048]
  const float* w = (const float*)d_in[1];     // [16, 2048, 384]
  float* out = (float*)d_out;                 // [2048, 2048]
  (void)in_sizes; (void)n_in; (void)out_size;

  cudaFuncSetAttribute(qkv_mma_kernel,
                       cudaFuncAttributeMaxDynamicSharedMemorySize, GEMM_SMEM);
  cudaFuncSetAttribute(attn_mma_kernel,
                       cudaFuncAttributeMaxDynamicSharedMemorySize, ATT_SMEM);

  convx_kernel<<<(SS * DD / 4) / 256, 256>>>(x);
  convw_kernel<<<dim3(NQKV / 32, DD / 32, HH), 256>>>(w);

  qkv_mma_kernel<<<dim3(NTOT / BN, SS / BM), 512, GEMM_SMEM>>>();

  attn_mma_kernel<<<dim3(SS / AQ, HH), 256, ATT_SMEM>>>(out);
}